// round 16
// baseline (speedup 1.0000x reference)
#include <cuda_runtime.h>
#include <math.h>

// ---------------------------------------------------------------------------
// RPN forward, batch -1 only.
// Winograd F(2x2,3x3): prep_x (V=B^T d B) + prep_w (U=G g G^T) -> 16 batched
// fp32 GEMMs (128x128 tiles, 8x8/thread) -> output transform + bias + leaky
// -> head GEMM + decode + histogram -> bucket prefix -> scatter -> exact
// local rank -> NMS mask (yy2=max bug) -> chunk scan WITH EARLY EXIT at 300
// kept -> 300x4 output.
// ---------------------------------------------------------------------------

#define FSZ   50
#define NCH   512
#define NKEYS 22500
#define PRE_NMS 6000
#define POST_NMS 300
#define NWORDS 188
#define NBUCK 65536

#define NTIL  625
#define NTP   640

__device__ float g_V[16 * NCH * NTP];              // [xi][ic][tile]
__device__ float g_U[16 * NCH * NCH];              // [xi][ic][oc]
__device__ float g_M[16 * NTP * NCH];              // [xi][tile][oc]
__device__ float g_feat[FSZ * FSZ * NCH];          // [s][oc]
__device__ float4 g_boxes[NKEYS];
__device__ unsigned g_hi[NKEYS];
__device__ unsigned g_hist[NBUCK];
__device__ unsigned g_bcnt[NBUCK];
__device__ unsigned g_bstart[NBUCK + 1];
__device__ unsigned long long g_skey[NKEYS];
__device__ int    g_C;
__device__ float4 g_sboxes[PRE_NMS];
__device__ unsigned g_mask[PRE_NMS * NWORDS];

// ---------------------------------------------------------------------------
__global__ void prep_x(const float* __restrict__ in) {
    int idx = blockIdx.x * blockDim.x + threadIdx.x;
    if (idx >= NCH * NTP) return;
    int ic = idx / NTP, tile = idx - ic * NTP;
    if (tile >= NTIL) return;
    int ty = tile / 25, tx = tile - ty * 25;

    const float* src = in + ((size_t)(7 * NCH + ic)) * 2500;
    float d[4][4];
#pragma unroll
    for (int i = 0; i < 4; ++i) {
        int py = 2 * ty + i - 1;
#pragma unroll
        for (int j = 0; j < 4; ++j) {
            int px = 2 * tx + j - 1;
            d[i][j] = (py >= 0 && py < 50 && px >= 0 && px < 50)
                      ? src[py * 50 + px] : 0.0f;
        }
    }
    float t[4][4];
#pragma unroll
    for (int j = 0; j < 4; ++j) {
        t[0][j] = d[0][j] - d[2][j];
        t[1][j] = d[1][j] + d[2][j];
        t[2][j] = d[2][j] - d[1][j];
        t[3][j] = d[1][j] - d[3][j];
    }
#pragma unroll
    for (int i = 0; i < 4; ++i) {
        float v0 = t[i][0] - t[i][2];
        float v1 = t[i][1] + t[i][2];
        float v2 = t[i][2] - t[i][1];
        float v3 = t[i][1] - t[i][3];
        g_V[((size_t)(i * 4 + 0) * NCH + ic) * NTP + tile] = v0;
        g_V[((size_t)(i * 4 + 1) * NCH + ic) * NTP + tile] = v1;
        g_V[((size_t)(i * 4 + 2) * NCH + ic) * NTP + tile] = v2;
        g_V[((size_t)(i * 4 + 3) * NCH + ic) * NTP + tile] = v3;
    }
}

__global__ void prep_w(const float* __restrict__ w) {
    int idx = blockIdx.x * blockDim.x + threadIdx.x;
    if (idx < NBUCK) { g_hist[idx] = 0u; g_bcnt[idx] = 0u; }
    if (idx >= NCH * NCH) return;
    int oc = idx & 511, ic = idx >> 9;

    const float* gp = w + ((size_t)oc * NCH + ic) * 9;
    float g[3][3];
#pragma unroll
    for (int i = 0; i < 3; ++i)
#pragma unroll
        for (int j = 0; j < 3; ++j) g[i][j] = gp[i * 3 + j];

    float T[4][3];
#pragma unroll
    for (int j = 0; j < 3; ++j) {
        T[0][j] = g[0][j];
        T[1][j] = 0.5f * (g[0][j] + g[1][j] + g[2][j]);
        T[2][j] = 0.5f * (g[0][j] - g[1][j] + g[2][j]);
        T[3][j] = g[2][j];
    }
#pragma unroll
    for (int i = 0; i < 4; ++i) {
        float u0 = T[i][0];
        float u1 = 0.5f * (T[i][0] + T[i][1] + T[i][2]);
        float u2 = 0.5f * (T[i][0] - T[i][1] + T[i][2]);
        float u3 = T[i][2];
        g_U[((size_t)(i * 4 + 0) * NCH + ic) * NCH + oc] = u0;
        g_U[((size_t)(i * 4 + 1) * NCH + ic) * NCH + oc] = u1;
        g_U[((size_t)(i * 4 + 2) * NCH + ic) * NCH + oc] = u2;
        g_U[((size_t)(i * 4 + 3) * NCH + ic) * NCH + oc] = u3;
    }
}

// ---------------------------------------------------------------------------
// 16 batched GEMMs, 128oc x 128tile per CTA, 8x8 per thread (all-float4 LDS).
// grid=(5 tile-chunks, 4 oc-chunks, 16 xi), 256 threads.
// ---------------------------------------------------------------------------
__global__ void __launch_bounds__(256) wgemm_kernel() {
    __shared__ float As[32 * 128];    // [k][oc]
    __shared__ float Bs[32 * 128];    // [k][tile]

    const int tid = threadIdx.x;
    const int tx = tid & 15, ty = tid >> 4;
    const int xi = blockIdx.z;
    const int ocb = blockIdx.y * 128;
    const int tb  = blockIdx.x * 128;
    const float* U = g_U + (size_t)xi * NCH * NCH;
    const float* V = g_V + (size_t)xi * NCH * NTP;

    float acc[2][2][4][4];
#pragma unroll
    for (int pa = 0; pa < 2; ++pa)
#pragma unroll
        for (int pb = 0; pb < 2; ++pb)
#pragma unroll
            for (int i = 0; i < 4; ++i)
#pragma unroll
                for (int j = 0; j < 4; ++j) acc[pa][pb][i][j] = 0.0f;

    for (int k0 = 0; k0 < NCH; k0 += 32) {
#pragma unroll
        for (int it = 0; it < 4; ++it) {
            int idx = tid + it * 256;
            int row = idx >> 5, q = idx & 31;
            reinterpret_cast<float4*>(As)[idx] =
                *reinterpret_cast<const float4*>(&U[(size_t)(k0 + row) * NCH + ocb + q * 4]);
            reinterpret_cast<float4*>(Bs)[idx] =
                *reinterpret_cast<const float4*>(&V[(size_t)(k0 + row) * NTP + tb + q * 4]);
        }
        __syncthreads();

#pragma unroll 2
        for (int k = 0; k < 32; ++k) {
            float4 a0 = reinterpret_cast<const float4*>(As)[k * 32 + tx];
            float4 a1 = reinterpret_cast<const float4*>(As)[k * 32 + 16 + tx];
            float4 b0 = reinterpret_cast<const float4*>(Bs)[k * 32 + ty];
            float4 b1 = reinterpret_cast<const float4*>(Bs)[k * 32 + 16 + ty];
            const float av[2][4] = {{a0.x, a0.y, a0.z, a0.w}, {a1.x, a1.y, a1.z, a1.w}};
            const float bv[2][4] = {{b0.x, b0.y, b0.z, b0.w}, {b1.x, b1.y, b1.z, b1.w}};
#pragma unroll
            for (int pa = 0; pa < 2; ++pa)
#pragma unroll
                for (int pb = 0; pb < 2; ++pb)
#pragma unroll
                    for (int i = 0; i < 4; ++i)
#pragma unroll
                        for (int j = 0; j < 4; ++j)
                            acc[pa][pb][i][j] += av[pa][i] * bv[pb][j];
        }
        __syncthreads();
    }

#pragma unroll
    for (int pb = 0; pb < 2; ++pb)
#pragma unroll
        for (int j = 0; j < 4; ++j) {
            int tile = tb + pb * 64 + ty * 4 + j;
#pragma unroll
            for (int pa = 0; pa < 2; ++pa) {
                float4 v = make_float4(acc[pa][pb][0][j], acc[pa][pb][1][j],
                                       acc[pa][pb][2][j], acc[pa][pb][3][j]);
                *reinterpret_cast<float4*>(
                    &g_M[((size_t)xi * NTP + tile) * NCH + ocb + pa * 64 + tx * 4]) = v;
            }
        }
}

// ---------------------------------------------------------------------------
__global__ void outtr_kernel(const float* __restrict__ bias) {
    int idx = blockIdx.x * blockDim.x + threadIdx.x;
    if (idx >= NTIL * NCH) return;
    int oc = idx & 511, tile = idx >> 9;
    int ty = tile / 25, tx = tile - ty * 25;

    float m[16];
#pragma unroll
    for (int xi = 0; xi < 16; ++xi)
        m[xi] = g_M[((size_t)xi * NTP + tile) * NCH + oc];

    float t0[4], t1[4];
#pragma unroll
    for (int j = 0; j < 4; ++j) {
        t0[j] = m[j] + m[4 + j] + m[8 + j];
        t1[j] = m[4 + j] - m[8 + j] - m[12 + j];
    }
    float y[2][2];
    y[0][0] = t0[0] + t0[1] + t0[2];
    y[0][1] = t0[1] - t0[2] - t0[3];
    y[1][0] = t1[0] + t1[1] + t1[2];
    y[1][1] = t1[1] - t1[2] - t1[3];

    float bv = bias[oc];
#pragma unroll
    for (int r = 0; r < 2; ++r)
#pragma unroll
        for (int c = 0; c < 2; ++c) {
            float v = y[r][c] + bv;
            v = (v >= 0.0f) ? v : 0.01f * v;
            int s = (2 * ty + r) * FSZ + (2 * tx + c);
            g_feat[(size_t)s * NCH + oc] = v;
        }
}

// ---------------------------------------------------------------------------
// Head (unchanged).
// ---------------------------------------------------------------------------
#define HB 16
#define WPAD 516
__global__ void __launch_bounds__(512) head_kernel(const float* __restrict__ rw,
                                                   const float* __restrict__ rb,
                                                   const float* __restrict__ cw,
                                                   const float* __restrict__ cb) {
    extern __shared__ float sh[];
    float* Wsp = sh;
    float* ft  = sh + 54 * WPAD;
    __shared__ float bb[54];
    __shared__ float par[2 * HB * 54];
    __shared__ float vals[HB * 54];

    const int tid = threadIdx.x;
    const int s0 = blockIdx.x * HB;

    for (int e = tid; e < 54 * NCH; e += 512) {
        int o = e >> 9, k = e & 511;
        Wsp[o * WPAD + k] = (o < 36) ? rw[o * NCH + k] : cw[(o - 36) * NCH + k];
    }
    if (tid < 54) bb[tid] = (tid < 36) ? rb[tid] : cb[tid - 36];
    for (int e = tid; e < HB * (NCH / 4); e += 512) {
        int sl = e >> 7, k4 = e & 127;
        int s = s0 + sl;
        float4 v = make_float4(0.f, 0.f, 0.f, 0.f);
        if (s < FSZ * FSZ) v = reinterpret_cast<const float4*>(g_feat + (size_t)s * NCH)[k4];
        reinterpret_cast<float4*>(ft + sl * NCH)[k4] = v;
    }
    __syncthreads();

    const int o  = tid & 63;
    const int r  = tid >> 6;
    const int kh = r >> 2;
    const int sg = r & 3;
    if (o < 54) {
        const float4* w4 = reinterpret_cast<const float4*>(Wsp + o * WPAD) + kh * 64;
        const float4* f0 = reinterpret_cast<const float4*>(ft + (sg * 4 + 0) * NCH) + kh * 64;
        const float4* f1 = reinterpret_cast<const float4*>(ft + (sg * 4 + 1) * NCH) + kh * 64;
        const float4* f2 = reinterpret_cast<const float4*>(ft + (sg * 4 + 2) * NCH) + kh * 64;
        const float4* f3 = reinterpret_cast<const float4*>(ft + (sg * 4 + 3) * NCH) + kh * 64;
        float a0 = 0.f, a1 = 0.f, a2 = 0.f, a3 = 0.f;
#pragma unroll 4
        for (int c = 0; c < 64; ++c) {
            float4 w = w4[c];
            float4 f = f0[c];
            a0 += w.x * f.x; a0 += w.y * f.y; a0 += w.z * f.z; a0 += w.w * f.w;
            f = f1[c];
            a1 += w.x * f.x; a1 += w.y * f.y; a1 += w.z * f.z; a1 += w.w * f.w;
            f = f2[c];
            a2 += w.x * f.x; a2 += w.y * f.y; a2 += w.z * f.z; a2 += w.w * f.w;
            f = f3[c];
            a3 += w.x * f.x; a3 += w.y * f.y; a3 += w.z * f.z; a3 += w.w * f.w;
        }
        par[(kh * HB + sg * 4 + 0) * 54 + o] = a0;
        par[(kh * HB + sg * 4 + 1) * 54 + o] = a1;
        par[(kh * HB + sg * 4 + 2) * 54 + o] = a2;
        par[(kh * HB + sg * 4 + 3) * 54 + o] = a3;
    }
    __syncthreads();

    for (int e = tid; e < HB * 54; e += 512) {
        int oo = e % 54;
        vals[e] = (par[e] + par[HB * 54 + e]) + bb[oo];
    }
    __syncthreads();

    if (tid < HB * 9) {
        int sl = tid / 9, a = tid - sl * 9;
        int s = s0 + sl;
        if (s < FSZ * FSZ) {
            const float* v = &vals[sl * 54];
            float pr0 = v[a * 4 + 0], pr1 = v[a * 4 + 1];
            float pr2 = v[a * 4 + 2], pr3 = v[a * 4 + 3];
            float l0 = v[36 + a * 2], l1 = v[36 + a * 2 + 1];
            float m = fmaxf(l0, l1);
            float e0 = expf(l0 - m), e1 = expf(l1 - m);
            float score = e1 / (e0 + e1);

            int hh = s / FSZ, ww = s - hh * FSZ;
            float cx = (float)(16 * hh + 8);
            float cy = (float)(16 * ww + 8);
            int rr = a / 3, q = a - rr * 3;
            float basev = (q == 0) ? 128.0f : (q == 1 ? 256.0f : 512.0f);
            float sq_r  = (rr == 0) ? sqrtf(0.5f) : (rr == 1 ? 1.0f : sqrtf(2.0f));
            float sq_ir = (rr == 0) ? sqrtf(2.0f) : (rr == 1 ? 1.0f : sqrtf(0.5f));
            float hsv = basev * sq_r;
            float wsv = basev * sq_ir;
            float ax1 = cx - wsv * 0.5f;
            float ay1 = cy - hsv * 0.5f;

            float t1 = pr0 + ax1;
            float t2 = pr1 + ay1;
            float rx1 = fminf(fmaxf(t1, 0.0f), 799.0f);
            float ry1 = fminf(fmaxf(t2, 0.0f), 799.0f);
            float rx2 = fminf(fmaxf((t1 + pr2) + wsv, 0.0f), 799.0f);
            float ry2 = fminf(fmaxf((t2 + pr3) + hsv, 0.0f), 799.0f);

            float wv = pr2 + wsv, hv = pr3 + hsv;
            bool valid = (wv >= 16.0f) && (hv >= 16.0f);
            float sm = valid ? score : -INFINITY;

            unsigned u = __float_as_uint(sm);
            unsigned vm = (u & 0x80000000u) ? ~u : (u | 0x80000000u);
            unsigned hi = ~vm;
            int gi = s * 9 + a;
            g_hi[gi] = hi;
            atomicAdd(&g_hist[hi >> 16], 1u);
            g_boxes[gi] = make_float4(rx1, ry1, rx2, ry2);
        }
    }
}

// ---------------------------------------------------------------------------
__global__ void __launch_bounds__(1024) prefix_kernel() {
    const int tid = threadIdx.x;
    const int base = tid * 64;
    unsigned sum = 0;
    for (int k = 0; k < 64; ++k) sum += g_hist[base + k];

    unsigned lane = tid & 31, w = tid >> 5;
    unsigned inc = sum;
#pragma unroll
    for (int d = 1; d < 32; d <<= 1) {
        unsigned n = __shfl_up_sync(0xFFFFFFFFu, inc, d);
        if (lane >= d) inc += n;
    }
    __shared__ unsigned wsum[32];
    if (lane == 31) wsum[w] = inc;
    __syncthreads();
    if (w == 0) {
        unsigned x = wsum[lane];
#pragma unroll
        for (int d = 1; d < 32; d <<= 1) {
            unsigned n = __shfl_up_sync(0xFFFFFFFFu, x, d);
            if (lane >= d) x += n;
        }
        wsum[lane] = x;
    }
    __syncthreads();
    unsigned run = inc - sum + (w ? wsum[w - 1] : 0u);
    for (int k = 0; k < 64; ++k) {
        unsigned hcount = g_hist[base + k];
        g_bstart[base + k] = run;
        unsigned nx = run + hcount;
        if (run < PRE_NMS && nx >= PRE_NMS) g_C = (int)nx;
        run = nx;
    }
    if (tid == 1023) g_bstart[NBUCK] = run;
}

__global__ void __launch_bounds__(256) scatter_kernel() {
    int i = blockIdx.x * 256 + threadIdx.x;
    if (i >= NKEYS) return;
    unsigned hi = g_hi[i];
    unsigned b = hi >> 16;
    unsigned st = g_bstart[b];
    if (st < PRE_NMS) {
        unsigned pos = st + atomicAdd(&g_bcnt[b], 1u);
        g_skey[pos] = ((unsigned long long)hi << 15) | (unsigned)i;
    }
}

__global__ void __launch_bounds__(256) localrank_kernel() {
    int p = blockIdx.x * 256 + threadIdx.x;
    if (p >= g_C) return;
    unsigned long long key = g_skey[p];
    unsigned hi = (unsigned)(key >> 15);
    unsigned b = hi >> 16;
    int s = (int)g_bstart[b], e = (int)g_bstart[b + 1];
    int r = s;
    for (int q = s; q < e; ++q) r += (g_skey[q] < key) ? 1 : 0;
    if (r < PRE_NMS) g_sboxes[r] = g_boxes[key & 0x7FFFu];
}

// ---------------------------------------------------------------------------
__global__ void __launch_bounds__(32) mask_kernel() {
    const int bi = blockIdx.y, bj = blockIdx.x;
    if (bj < bi) return;
    const int t = threadIdx.x;
    const int i = bi * 32 + t;

    __shared__ float4 bx[32];
    __shared__ float ar[32];
    const int j0 = bj * 32;
    if (j0 + t < PRE_NMS) {
        float4 b = g_sboxes[j0 + t];
        bx[t] = b;
        ar[t] = ((b.z - b.x) + 1.0f) * ((b.w - b.y) + 1.0f);
    }
    __syncwarp();
    if (i >= PRE_NMS) return;

    float4 bi4 = g_sboxes[i];
    float areai = ((bi4.z - bi4.x) + 1.0f) * ((bi4.w - bi4.y) + 1.0f);
    unsigned word = 0;
    int jmax = min(32, PRE_NMS - j0);
    for (int jj = 0; jj < jmax; ++jj) {
        int jg = j0 + jj;
        if (jg <= i) continue;
        float4 bj4 = bx[jj];
        float xx1 = fmaxf(bi4.x, bj4.x);
        float yy1 = fmaxf(bi4.y, bj4.y);
        float xx2 = fminf(bi4.z, bj4.z);
        float yy2 = fmaxf(bi4.w, bj4.w);              // reference bug
        float w = fmaxf(0.0f, (xx2 - xx1) + 1.0f);
        float h = fmaxf(0.0f, (yy2 - yy1) + 1.0f);
        float inter = w * h;
        float ov = inter / ((areai + ar[jj]) - inter);
        if (ov > 0.7f) word |= (1u << jj);
    }
    g_mask[i * NWORDS + bj] = word;
}

// ---------------------------------------------------------------------------
// Chunk scan with EARLY EXIT: once >=300 boxes are kept, all later chunks
// and all suppressed boxes map to output pos >= 300 and are irrelevant.
// ---------------------------------------------------------------------------
__global__ void __launch_bounds__(256) scan_kernel(float* __restrict__ out) {
    __shared__ unsigned keep[NWORDS];
    __shared__ unsigned sdiag[32];
    __shared__ unsigned curAlive;
    __shared__ int keptTot;
    __shared__ int cutw;
    __shared__ int pref[NWORDS + 1];
    const int tid = threadIdx.x;
    if (tid < NWORDS) keep[tid] = (tid == NWORDS - 1) ? 0x0000FFFFu : 0xFFFFFFFFu;
    if (tid == 0) { keptTot = 0; cutw = NWORDS; }
    __syncthreads();

    for (int c = 0; c < NWORDS; ++c) {
        if (tid < 32) {
            int i = c * 32 + tid;
            sdiag[tid] = (i < PRE_NMS) ? g_mask[i * NWORDS + c] : 0u;
            __syncwarp();
            if (tid == 0) {
                unsigned alive = keep[c];
                unsigned rem = alive;
                while (rem) {
                    int b = __ffs(rem) - 1;
                    rem &= rem - 1u;
                    alive &= ~sdiag[b];
                    rem &= alive;
                }
                keep[c] = alive;
                curAlive = alive;
                keptTot += __popc(alive);
                if (keptTot >= POST_NMS) cutw = c + 1;
            }
        }
        __syncthreads();
        if (cutw != NWORDS) break;                 // enough keepers determined
        unsigned alive = curAlive;
        if (alive) {
            for (int w2 = c + 1 + tid; w2 < NWORDS; w2 += 256) {
                unsigned nm = 0;
                unsigned a = alive;
                while (a) {
                    int b = __ffs(a) - 1;
                    a &= a - 1u;
                    nm |= g_mask[(c * 32 + b) * NWORDS + w2];
                }
                keep[w2] &= ~nm;
            }
        }
        __syncthreads();
    }

    const int CW = cutw;                           // words with valid keep state
    if (tid == 0) {
        int run = 0;
        pref[0] = 0;
        for (int w = 0; w < CW; ++w) { run += __popc(keep[w]); pref[w + 1] = run; }
    }
    __syncthreads();
    const int K = pref[CW];

    for (int i = tid; i < CW * 32 && i < PRE_NMS; i += 256) {
        int w = i >> 5, b = i & 31;
        unsigned kwv = keep[w];
        int kp = pref[w] + __popc(kwv & ((1u << b) - 1u));
        int pos = ((kwv >> b) & 1u) ? kp : (K + (i - kp));
        if (pos < POST_NMS) {
            float4 bb = g_sboxes[i];
            out[pos * 4 + 0] = bb.x;
            out[pos * 4 + 1] = bb.y;
            out[pos * 4 + 2] = (bb.z - bb.x) + 1.0f;
            out[pos * 4 + 3] = (bb.w - bb.y) + 1.0f;
        }
    }
}

// ---------------------------------------------------------------------------
extern "C" void kernel_launch(void* const* d_in, const int* in_sizes, int n_in,
                              void* d_out, int out_size) {
    const float* in_features = (const float*)d_in[0];
    const float* conv_w      = (const float*)d_in[1];
    const float* conv_b      = (const float*)d_in[2];
    const float* reg_w       = (const float*)d_in[3];
    const float* reg_b       = (const float*)d_in[4];
    const float* cls_w       = (const float*)d_in[5];
    const float* cls_b       = (const float*)d_in[6];
    float* out = (float*)d_out;

    const int head_smem = (54 * WPAD + HB * NCH) * (int)sizeof(float);
    cudaFuncSetAttribute(head_kernel, cudaFuncAttributeMaxDynamicSharedMemorySize, head_smem);

    prep_x<<<(NCH * NTP + 255) / 256, 256>>>(in_features);
    prep_w<<<(NCH * NCH + 255) / 256, 256>>>(conv_w);
    wgemm_kernel<<<dim3(5, 4, 16), 256>>>();
    outtr_kernel<<<(NTIL * NCH + 255) / 256, 256>>>(conv_b);
    head_kernel<<<(FSZ * FSZ + HB - 1) / HB, 512, head_smem>>>(reg_w, reg_b, cls_w, cls_b);
    prefix_kernel<<<1, 1024>>>();
    scatter_kernel<<<(NKEYS + 255) / 256, 256>>>();
    localrank_kernel<<<(NKEYS + 255) / 256, 256>>>();
    mask_kernel<<<dim3(NWORDS, NWORDS), 32>>>();
    scan_kernel<<<1, 256>>>(out);
}